// round 8
// baseline (speedup 1.0000x reference)
#include <cuda_runtime.h>
#include <cuda_fp16.h>
#include <cstdint>
#include <cstddef>

#define SEQ 65536
#define HID 128
#define NG  512
#define INP 64

// Permuted x-gate scratch (+2 steps padding for unguarded prefetch)
static __device__ float g_xg[(size_t)(SEQ + 2) * NG];

union F2U { float2 f; unsigned long long u; };
union H4U { float4 v; __half2 h[4]; };

static __device__ __forceinline__ unsigned long long ld2(const float2* p) {
    F2U u; u.f = *p; return u.u;
}
static __device__ __forceinline__ unsigned long long ffma2(unsigned long long a,
                                                           unsigned long long b,
                                                           unsigned long long c) {
    unsigned long long d;
    asm("fma.rn.f32x2 %0, %1, %2, %3;" : "=l"(d) : "l"(a), "l"(b), "l"(c));
    return d;
}
static __device__ __forceinline__ unsigned long long fadd2(unsigned long long a,
                                                           unsigned long long b) {
    unsigned long long d;
    asm("add.rn.f32x2 %0, %1, %2;" : "=l"(d) : "l"(a), "l"(b));
    return d;
}
static __device__ __forceinline__ float hsum2(unsigned long long a) {
    F2U u; u.u = a; return u.f.x + u.f.y;
}
static __device__ __forceinline__ float ftanh(float x) {
    float y; asm("tanh.approx.f32 %0, %1;" : "=f"(y) : "f"(x)); return y;
}

// ---------------------------------------------------------------------------
// Phase 1: x_gates, permuted for the 1024-thread scan:
//   row r = gate*128 + j   (gate=r>>7, j=r&127)
//   slot  = (j>>2)*16 + gate*4 + (j&3)
// Each scan warp then reads slots [w*16, w*16+16) — one 64B line.
// ---------------------------------------------------------------------------
__global__ void __launch_bounds__(512, 1)
gemm_xg(const float* __restrict__ x, const float* __restrict__ Wih,
        const float* __restrict__ bih, const float* __restrict__ bhh)
{
    __shared__ __align__(16) float xs[128 * INP];
    const int r  = threadIdx.x;
    const int t0 = blockIdx.x * 128;

    {
        const float4* src = (const float4*)(x + (size_t)t0 * INP);
        float4* dst = (float4*)xs;
        #pragma unroll
        for (int i = r; i < 128 * INP / 4; i += 512) dst[i] = src[i];
    }

    unsigned long long w[32];
    {
        const float2* wr = (const float2*)(Wih + (size_t)r * INP);
        #pragma unroll
        for (int i = 0; i < 32; i++) w[i] = ld2(wr + i);
    }
    const float bias = bih[r] + bhh[r];

    const int gate = r >> 7, j = r & 127;
    const int slot = (j >> 2) * 16 + gate * 4 + (j & 3);
    __syncthreads();

    for (int tt = 0; tt < 128; tt++) {
        const float2* xp = (const float2*)(xs + tt * INP);
        unsigned long long a0 = 0ull, a1 = 0ull, a2 = 0ull, a3 = 0ull;
        #pragma unroll
        for (int i = 0; i < 32; i += 4) {
            a0 = ffma2(w[i + 0], ld2(xp + i + 0), a0);
            a1 = ffma2(w[i + 1], ld2(xp + i + 1), a1);
            a2 = ffma2(w[i + 2], ld2(xp + i + 2), a2);
            a3 = ffma2(w[i + 3], ld2(xp + i + 3), a3);
        }
        g_xg[(size_t)(t0 + tt) * NG + slot] =
            hsum2(fadd2(fadd2(a0, a1), fadd2(a2, a3))) + bias;
    }
}

// ---------------------------------------------------------------------------
// Phase 2+3: single-CTA scan, 1024 threads, 2 threads per gate row (k-split
// within a warp). Warp w covers all 4 gates of j in [4w, 4w+4).
//   lane = khalf*16 + gate*4 + j2    (khalf = lane>>4, p = lane&15)
// Partial combine: shfl_xor(16). Gate gather: shfl from p, p+4, p+8, p+12.
// W_hh half-row (64 f16 = 32 half2) per thread in registers.
// ---------------------------------------------------------------------------
__global__ void __launch_bounds__(1024, 1)
lstm_scan(const float* __restrict__ Whh,
          const float* __restrict__ Wlin,
          const float* __restrict__ blin,
          float* __restrict__ out)
{
    __shared__ __align__(16) __half h_s[2][HID];

    const int tid   = threadIdx.x;
    const int w_id  = tid >> 5;
    const int lane  = tid & 31;
    const int khalf = lane >> 4;
    const int p     = lane & 15;
    const int gate  = p >> 2;
    const int j2    = p & 3;
    const int j     = w_id * 4 + j2;
    const int row   = gate * HID + j;

    // This thread's 64-wide k-half of its row, as 32 half2 registers
    __half2 w[32];
    {
        const float2* wr =
            (const float2*)(Whh + (size_t)row * HID + khalf * 64);
        #pragma unroll
        for (int i = 0; i < 32; i++) w[i] = __float22half2_rn(wr[i]);
    }

    if (tid < 2 * HID) ((__half*)h_s)[tid] = __float2half_rn(0.0f);

    // activation: y = aa*tanh(kk*s)+bb  (sigmoid(x) = 0.5 + 0.5*tanh(x/2))
    const float kk = (gate == 2) ? 1.0f : 0.5f;
    const float aa = (gate == 2) ? 1.0f : 0.5f;
    const float bb = (gate == 2) ? 0.0f : 0.5f;

    float c = 0.0f;
    const float* xq = g_xg + w_id * 16 + p;
    float xcur[2];
    xcur[0] = xq[0];
    xcur[1] = xq[NG];

    __syncthreads();

#define STEP(B)                                                                \
    {                                                                          \
        const float4* hp =                                                     \
            (const float4*)(h_s[(B) ^ 1] + khalf * 64);                        \
        __half2 a0 = __float2half2_rn(0.0f), a1 = a0, a2 = a0, a3 = a0;        \
        _Pragma("unroll")                                                      \
        for (int i = 0; i < 8; i++) {                                          \
            H4U q; q.v = hp[i];                                                \
            a0 = __hfma2(w[4 * i + 0], q.h[0], a0);                            \
            a1 = __hfma2(w[4 * i + 1], q.h[1], a1);                            \
            a2 = __hfma2(w[4 * i + 2], q.h[2], a2);                            \
            a3 = __hfma2(w[4 * i + 3], q.h[3], a3);                            \
        }                                                                      \
        a0 = __hadd2(a0, a1);                                                  \
        a2 = __hadd2(a2, a3);                                                  \
        a0 = __hadd2(a0, a2);                                                  \
        const float part = __low2float(a0) + __high2float(a0);                 \
        const float s = xcur[B] + part +                                       \
                        __shfl_xor_sync(0xffffffffu, part, 16);                \
        xcur[B] = xq[2 * NG];                                                  \
        xq += NG;                                                              \
        const float y = fmaf(aa, ftanh(kk * s), bb);                           \
        const float iv = __shfl_sync(0xffffffffu, y, j2);                      \
        const float fv = __shfl_sync(0xffffffffu, y, j2 + 4);                  \
        const float gv = __shfl_sync(0xffffffffu, y, j2 + 8);                  \
        const float ov = __shfl_sync(0xffffffffu, y, j2 + 12);                 \
        c = fmaf(fv, c, iv * gv);                                              \
        const float hv = ov * ftanh(c);                                        \
        if (lane < 4) h_s[B][w_id * 4 + lane] = __float2half_rn(hv);           \
        __syncthreads();                                                       \
    }

    for (int t = 0; t < SEQ; t += 2) {
        STEP(0)
        STEP(1)
    }

    // h_T in h_s[1]; warp 0 reduces the linear head.
    if (tid < 32) {
        float s = 0.0f;
        #pragma unroll
        for (int m = 0; m < 4; m++)
            s += __half2float(h_s[1][lane + 32 * m]) * Wlin[lane + 32 * m];
        #pragma unroll
        for (int d = 16; d > 0; d >>= 1)
            s += __shfl_xor_sync(0xffffffffu, s, d);
        if (lane == 0)
            out[0] = fmaf(0.5f, ftanh(0.5f * (s + blin[0])), 0.5f);
    }
}

extern "C" void kernel_launch(void* const* d_in, const int* in_sizes, int n_in,
                              void* d_out, int out_size) {
    const float* input = (const float*)d_in[0];
    const float* Wih   = (const float*)d_in[1];
    const float* Whh   = (const float*)d_in[2];
    const float* bih   = (const float*)d_in[3];
    const float* bhh   = (const float*)d_in[4];
    const float* Wlin  = (const float*)d_in[5];
    const float* blin  = (const float*)d_in[6];
    float* out = (float*)d_out;

    gemm_xg<<<SEQ / 128, 512>>>(input, Wih, bih, bhh);
    lstm_scan<<<1, 1024>>>(Whh, Wlin, blin, out);
}

// round 10
// speedup vs baseline: 1.1351x; 1.1351x over previous
#include <cuda_runtime.h>
#include <cuda_fp16.h>
#include <cstdint>
#include <cstddef>

#define SEQ 65536
#define HID 128
#define NG  512
#define INP 64

// Permuted x-gate scratch (+2 steps padding for unguarded prefetch)
static __device__ float g_xg[(size_t)(SEQ + 2) * NG];

union F2U { float2 f; unsigned long long u; };
union H4U { float4 v; __half2 h[4]; };

static __device__ __forceinline__ unsigned long long ld2(const float2* p) {
    F2U u; u.f = *p; return u.u;
}
static __device__ __forceinline__ unsigned long long ffma2(unsigned long long a,
                                                           unsigned long long b,
                                                           unsigned long long c) {
    unsigned long long d;
    asm("fma.rn.f32x2 %0, %1, %2, %3;" : "=l"(d) : "l"(a), "l"(b), "l"(c));
    return d;
}
static __device__ __forceinline__ unsigned long long fadd2(unsigned long long a,
                                                           unsigned long long b) {
    unsigned long long d;
    asm("add.rn.f32x2 %0, %1, %2;" : "=l"(d) : "l"(a), "l"(b));
    return d;
}
static __device__ __forceinline__ float hsum2(unsigned long long a) {
    F2U u; u.u = a; return u.f.x + u.f.y;
}
static __device__ __forceinline__ float ftanh(float x) {
    float y; asm("tanh.approx.f32 %0, %1;" : "=f"(y) : "f"(x)); return y;
}

// ---------------------------------------------------------------------------
// Phase 1: x_gates, permuted for the 256-thread scan.
//   row r = gate*128 + j.  hb = j>>6 (column half), jj = j&63,
//   slot = (jj>>3)*64 + (gate*8 + (jj&7))*2 + hb
// Scan thread (w, lane): one LDG.64 gives (xgA, xgB) for its two columns.
// ---------------------------------------------------------------------------
__global__ void __launch_bounds__(512, 1)
gemm_xg(const float* __restrict__ x, const float* __restrict__ Wih,
        const float* __restrict__ bih, const float* __restrict__ bhh)
{
    __shared__ __align__(16) float xs[128 * INP];
    const int r  = threadIdx.x;
    const int t0 = blockIdx.x * 128;

    {
        const float4* src = (const float4*)(x + (size_t)t0 * INP);
        float4* dst = (float4*)xs;
        #pragma unroll
        for (int i = r; i < 128 * INP / 4; i += 512) dst[i] = src[i];
    }

    unsigned long long w[32];
    {
        const float2* wr = (const float2*)(Wih + (size_t)r * INP);
        #pragma unroll
        for (int i = 0; i < 32; i++) w[i] = ld2(wr + i);
    }
    const float bias = bih[r] + bhh[r];

    const int gate = r >> 7, j = r & 127;
    const int hb = j >> 6, jj = j & 63;
    const int slot = (jj >> 3) * 64 + (gate * 8 + (jj & 7)) * 2 + hb;
    __syncthreads();

    for (int tt = 0; tt < 128; tt++) {
        const float2* xp = (const float2*)(xs + tt * INP);
        unsigned long long a0 = 0ull, a1 = 0ull, a2 = 0ull, a3 = 0ull;
        #pragma unroll
        for (int i = 0; i < 32; i += 4) {
            a0 = ffma2(w[i + 0], ld2(xp + i + 0), a0);
            a1 = ffma2(w[i + 1], ld2(xp + i + 1), a1);
            a2 = ffma2(w[i + 2], ld2(xp + i + 2), a2);
            a3 = ffma2(w[i + 3], ld2(xp + i + 3), a3);
        }
        g_xg[(size_t)(t0 + tt) * NG + slot] =
            hsum2(fadd2(fadd2(a0, a1), fadd2(a2, a3))) + bias;
    }
}

// ---------------------------------------------------------------------------
// Phase 2+3: single-CTA scan, 256 threads, 2 gate rows per thread.
// Warp w (0..7), lane l: gate = l>>3, jsub = l&7.
//   column A: jA = w*8+jsub (0..63), row rA = gate*128+jA
//   column B: jB = 64+jA,            row rB = gate*128+jB
// FULL rows in registers: wa[64], wb[64] half2 (128 f16 each).
// h loaded once per thread (16 LDS.128), feeds both rows' dot products.
// ---------------------------------------------------------------------------
__global__ void __launch_bounds__(256, 1)
lstm_scan(const float* __restrict__ Whh,
          const float* __restrict__ Wlin,
          const float* __restrict__ blin,
          float* __restrict__ out)
{
    __shared__ __align__(16) __half h_s[2][HID];

    const int tid  = threadIdx.x;
    const int w_id = tid >> 5;
    const int lane = tid & 31;
    const int gate = lane >> 3;
    const int jsub = lane & 7;
    const int jA   = w_id * 8 + jsub;
    const int rA   = gate * HID + jA;
    const int rB   = rA + 64;

    // Two FULL W_hh rows as half2 registers (64 + 64 = 128 regs)
    __half2 wa[64], wb[64];
    {
        const float2* pa = (const float2*)(Whh + (size_t)rA * HID);
        const float2* pb = (const float2*)(Whh + (size_t)rB * HID);
        #pragma unroll
        for (int i = 0; i < 64; i++) wa[i] = __float22half2_rn(pa[i]);
        #pragma unroll
        for (int i = 0; i < 64; i++) wb[i] = __float22half2_rn(pb[i]);
    }

    if (tid < 2 * HID) ((__half*)h_s)[tid] = __float2half_rn(0.0f);

    // activation: y = aa*tanh(kk*s)+bb  (sigmoid(x) = 0.5 + 0.5*tanh(x/2))
    const float kk = (gate == 2) ? 1.0f : 0.5f;
    const float aa = (gate == 2) ? 1.0f : 0.5f;
    const float bb = (gate == 2) ? 0.0f : 0.5f;

    float cA = 0.0f, cB = 0.0f;
    const float2* xq =
        (const float2*)(g_xg + w_id * 64 + (gate * 8 + jsub) * 2);
    float2 xcur[2];
    xcur[0] = xq[0];
    xcur[1] = xq[NG / 2];

    __syncthreads();

#define STEP(B)                                                                \
    {                                                                          \
        const float4* hp = (const float4*)h_s[(B) ^ 1];                        \
        __half2 z = __float2half2_rn(0.0f);                                    \
        __half2 aA0 = z, aA1 = z, aA2 = z, aA3 = z;                            \
        __half2 aB0 = z, aB1 = z, aB2 = z, aB3 = z;                            \
        _Pragma("unroll")                                                      \
        for (int i = 0; i < 16; i++) {                                         \
            H4U q; q.v = hp[i];                                                \
            aA0 = __hfma2(wa[4 * i + 0], q.h[0], aA0);                         \
            aA1 = __hfma2(wa[4 * i + 1], q.h[1], aA1);                         \
            aA2 = __hfma2(wa[4 * i + 2], q.h[2], aA2);                         \
            aA3 = __hfma2(wa[4 * i + 3], q.h[3], aA3);                         \
            aB0 = __hfma2(wb[4 * i + 0], q.h[0], aB0);                         \
            aB1 = __hfma2(wb[4 * i + 1], q.h[1], aB1);                         \
            aB2 = __hfma2(wb[4 * i + 2], q.h[2], aB2);                         \
            aB3 = __hfma2(wb[4 * i + 3], q.h[3], aB3);                         \
        }                                                                      \
        aA0 = __hadd2(aA0, aA1); aA2 = __hadd2(aA2, aA3);                      \
        aB0 = __hadd2(aB0, aB1); aB2 = __hadd2(aB2, aB3);                      \
        aA0 = __hadd2(aA0, aA2);                                               \
        aB0 = __hadd2(aB0, aB2);                                               \
        const float sA = xcur[B].x + __low2float(aA0) + __high2float(aA0);     \
        const float sB = xcur[B].y + __low2float(aB0) + __high2float(aB0);     \
        xcur[B] = xq[NG];                                                      \
        xq += NG / 2;                                                          \
        const float yA = fmaf(aa, ftanh(kk * sA), bb);                         \
        const float yB = fmaf(aa, ftanh(kk * sB), bb);                         \
        const float ivA = __shfl_sync(0xffffffffu, yA, jsub);                  \
        const float fvA = __shfl_sync(0xffffffffu, yA, jsub + 8);              \
        const float gvA = __shfl_sync(0xffffffffu, yA, jsub + 16);             \
        const float ovA = __shfl_sync(0xffffffffu, yA, jsub + 24);             \
        const float ivB = __shfl_sync(0xffffffffu, yB, jsub);                  \
        const float fvB = __shfl_sync(0xffffffffu, yB, jsub + 8);              \
        const float gvB = __shfl_sync(0xffffffffu, yB, jsub + 16);             \
        const float ovB = __shfl_sync(0xffffffffu, yB, jsub + 24);             \
        cA = fmaf(fvA, cA, ivA * gvA);                                         \
        cB = fmaf(fvB, cB, ivB * gvB);                                         \
        const float hvA = ovA * ftanh(cA);                                     \
        const float hvB = ovB * ftanh(cB);                                     \
        if (lane < 8) {                                                        \
            h_s[B][w_id * 8 + lane]      = __float2half_rn(hvA);               \
            h_s[B][64 + w_id * 8 + lane] = __float2half_rn(hvB);               \
        }                                                                      \
        __syncthreads();                                                       \
    }

    for (int t = 0; t < SEQ; t += 2) {
        STEP(0)
        STEP(1)
    }

    // h_T in h_s[1]; warp 0 reduces the linear head.
    if (tid < 32) {
        float s = 0.0f;
        #pragma unroll
        for (int m = 0; m < 4; m++)
            s += __half2float(h_s[1][lane + 32 * m]) * Wlin[lane + 32 * m];
        #pragma unroll
        for (int d = 16; d > 0; d >>= 1)
            s += __shfl_xor_sync(0xffffffffu, s, d);
        if (lane == 0)
            out[0] = fmaf(0.5f, ftanh(0.5f * (s + blin[0])), 0.5f);
    }
}

extern "C" void kernel_launch(void* const* d_in, const int* in_sizes, int n_in,
                              void* d_out, int out_size) {
    const float* input = (const float*)d_in[0];
    const float* Wih   = (const float*)d_in[1];
    const float* Whh   = (const float*)d_in[2];
    const float* bih   = (const float*)d_in[3];
    const float* bhh   = (const float*)d_in[4];
    const float* Wlin  = (const float*)d_in[5];
    const float* blin  = (const float*)d_in[6];
    float* out = (float*)d_out;

    gemm_xg<<<SEQ / 128, 512>>>(input, Wih, bih, bhh);
    lstm_scan<<<1, 256>>>(Whh, Wlin, blin, out);
}